// round 5
// baseline (speedup 1.0000x reference)
#include <cuda_runtime.h>
#include <cuda_bf16.h>

// DensityEstimator: per-channel 1->3->3->3->1 MLP, p = cdf(x+.5) - cdf(x-.5)
// R5: weights evicted from registers to SMEM so we get BOTH high occupancy
// (6 blocks/SM = 48 warps) AND 2-elem ILP (4 independent tanh chains/thread).
// Per-block weight transform into a bank-conflict-free table:
//   4 planes x 3 float4 per channel, channel stride 12 floats -> LDS.128
//   8-lane phases hit banks {0,12,24,4,16,28,8,20}+[0..3] = perfect partition.
// Both elements of an iteration share one set of weight loads (same channel).

#define NCH  192
#define NBLK 888          // 6 per SM; 888*256 = 227328 = 192*1184
#define NTHR 256

__device__ __forceinline__ float tanha(float x) {
    float r; asm("tanh.approx.f32 %0, %1;" : "=f"(r) : "f"(x)); return r;
}
__device__ __forceinline__ float softplus_acc(float h) {
    return (h > 15.0f) ? h : log1pf(expf(h));
}

__global__ void __launch_bounds__(NTHR, 6) de_kernel(
    const float* __restrict__ x,
    const float* __restrict__ a0, const float* __restrict__ a1, const float* __restrict__ a2,
    const float* __restrict__ b0, const float* __restrict__ b1, const float* __restrict__ b2,
    const float* __restrict__ b3,
    const float* __restrict__ H0, const float* __restrict__ H1, const float* __restrict__ H2,
    const float* __restrict__ H3,
    float* __restrict__ out, int n)
{
    // 4 planes x (192 ch x 3 float4). Plane stride 576 float4 = 9216 B.
    __shared__ float4 sw[4 * NCH * 3];     // 36864 B

    const int tid = threadIdx.x;

    // ---- Per-block weight transform (threads 0..191, one channel each) ----
    if (tid < NCH) {
        const int c = tid;
        float sh0[3], sh3[3], ta0[3], ta1[3], ta2[3];
        float bp0[3], bm0[3], bb1[3], bb2[3];
        float s1[9], s2[9];
#pragma unroll
        for (int j = 0; j < 3; j++) {
            sh0[j] = softplus_acc(H0[c*3 + j]);
            sh3[j] = 0.5f * softplus_acc(H3[c*3 + j]);     // 1/2 folded
            ta0[j] = tanhf(a0[c*3 + j]);
            ta1[j] = tanhf(a1[c*3 + j]);
            ta2[j] = tanhf(a2[c*3 + j]);
            float b0j = b0[c*3 + j];
            bp0[j] = fmaf( 0.5f, sh0[j], b0j);
            bm0[j] = fmaf(-0.5f, sh0[j], b0j);
            bb1[j] = b1[c*3 + j];
            bb2[j] = b2[c*3 + j];
        }
#pragma unroll
        for (int j = 0; j < 9; j++) {
            s1[j] = softplus_acc(H1[c*9 + j]);             // [i*3+p]
            s2[j] = softplus_acc(H2[c*9 + j]);
        }
        float bb3 = 0.5f * b3[c];                          // 1/2 folded

        const int c3 = c * 3;
        sw[          c3 + 0] = make_float4(sh0[0], sh0[1], sh0[2], bb3);
        sw[          c3 + 1] = make_float4(bp0[0], bp0[1], bp0[2], sh3[0]);
        sw[          c3 + 2] = make_float4(bm0[0], bm0[1], bm0[2], sh3[1]);
        sw[1*576 +   c3 + 0] = make_float4(ta0[0], ta0[1], ta0[2], sh3[2]);
        sw[1*576 +   c3 + 1] = make_float4(s1[0], s1[1], s1[2], s1[3]);
        sw[1*576 +   c3 + 2] = make_float4(s1[4], s1[5], s1[6], s1[7]);
        sw[2*576 +   c3 + 0] = make_float4(s1[8], ta1[0], ta1[1], ta1[2]);
        sw[2*576 +   c3 + 1] = make_float4(bb1[0], bb1[1], bb1[2], 0.0f);
        sw[2*576 +   c3 + 2] = make_float4(s2[0], s2[1], s2[2], s2[3]);
        sw[3*576 +   c3 + 0] = make_float4(s2[4], s2[5], s2[6], s2[7]);
        sw[3*576 +   c3 + 1] = make_float4(s2[8], ta2[0], ta2[1], ta2[2]);
        sw[3*576 +   c3 + 2] = make_float4(bb2[0], bb2[1], bb2[2], 0.0f);
    }
    __syncthreads();

    const int T  = gridDim.x * blockDim.x;          // 227328, multiple of 192
    const int i0 = blockIdx.x * blockDim.x + tid;
    const int c3 = (i0 % NCH) * 3;                  // fixed channel -> fixed smem addrs

    for (int i = i0; i < n; i += 2 * T) {
        const int  i2  = i + T;                     // same channel (T % 192 == 0)
        const bool ok2 = i2 < n;
        float xa = x[i];
        float xb = x[ok2 ? i2 : i];

        float4 w00 = sw[c3 + 0];                    // sh0, bb3
        float4 w01 = sw[c3 + 1];                    // bp0, sh3[0]
        float4 w02 = sw[c3 + 2];                    // bm0, sh3[1]
        float4 w10 = sw[576 + c3 + 0];              // ta0, sh3[2]

        // ---- Layer 0: 1 -> 3, both elements, p and m branches ----
        float ypA[3], ymA[3], ypB[3], ymB[3];
        {
            const float s0[3] = {w00.x, w00.y, w00.z};
            const float bp[3] = {w01.x, w01.y, w01.z};
            const float bm[3] = {w02.x, w02.y, w02.z};
            const float t0[3] = {w10.x, w10.y, w10.z};
#pragma unroll
            for (int j = 0; j < 3; j++) {
                float tpA = fmaf(xa, s0[j], bp[j]);
                float tmA = fmaf(xa, s0[j], bm[j]);
                float tpB = fmaf(xb, s0[j], bp[j]);
                float tmB = fmaf(xb, s0[j], bm[j]);
                ypA[j] = fmaf(t0[j], tanha(tpA), tpA);
                ymA[j] = fmaf(t0[j], tanha(tmA), tmA);
                ypB[j] = fmaf(t0[j], tanha(tpB), tpB);
                ymB[j] = fmaf(t0[j], tanha(tmB), tmB);
            }
        }

        float4 w11 = sw[576 + c3 + 1];              // sh1[0..3]
        float4 w12 = sw[576 + c3 + 2];              // sh1[4..7]
        float4 w20 = sw[1152 + c3 + 0];             // sh1[8], ta1
        float4 w21 = sw[1152 + c3 + 1];             // bb1

        // ---- Layer 1: 3 -> 3 ----
        float zpA[3], zmA[3], zpB[3], zmB[3];
        {
            const float s1[9] = {w11.x, w11.y, w11.z, w11.w,
                                 w12.x, w12.y, w12.z, w12.w, w20.x};
            const float t1[3] = {w20.y, w20.z, w20.w};
            const float bbv[3] = {w21.x, w21.y, w21.z};
#pragma unroll
            for (int p = 0; p < 3; p++) {
                float spA = bbv[p], smA = bbv[p], spB = bbv[p], smB = bbv[p];
#pragma unroll
                for (int j = 0; j < 3; j++) {
                    spA = fmaf(ypA[j], s1[j*3 + p], spA);
                    smA = fmaf(ymA[j], s1[j*3 + p], smA);
                    spB = fmaf(ypB[j], s1[j*3 + p], spB);
                    smB = fmaf(ymB[j], s1[j*3 + p], smB);
                }
                zpA[p] = fmaf(t1[p], tanha(spA), spA);
                zmA[p] = fmaf(t1[p], tanha(smA), smA);
                zpB[p] = fmaf(t1[p], tanha(spB), spB);
                zmB[p] = fmaf(t1[p], tanha(smB), smB);
            }
        }

        float4 w22 = sw[1152 + c3 + 2];             // sh2[0..3]
        float4 w30 = sw[1728 + c3 + 0];             // sh2[4..7]
        float4 w31 = sw[1728 + c3 + 1];             // sh2[8], ta2
        float4 w32 = sw[1728 + c3 + 2];             // bb2

        // ---- Layer 2: 3 -> 3 ----
        {
            const float s2[9] = {w22.x, w22.y, w22.z, w22.w,
                                 w30.x, w30.y, w30.z, w30.w, w31.x};
            const float t2[3] = {w31.y, w31.z, w31.w};
            const float bbv[3] = {w32.x, w32.y, w32.z};
#pragma unroll
            for (int p = 0; p < 3; p++) {
                float spA = bbv[p], smA = bbv[p], spB = bbv[p], smB = bbv[p];
#pragma unroll
                for (int j = 0; j < 3; j++) {
                    spA = fmaf(zpA[j], s2[j*3 + p], spA);
                    smA = fmaf(zmA[j], s2[j*3 + p], smA);
                    spB = fmaf(zpB[j], s2[j*3 + p], spB);
                    smB = fmaf(zmB[j], s2[j*3 + p], smB);
                }
                ypA[p] = fmaf(t2[p], tanha(spA), spA);
                ymA[p] = fmaf(t2[p], tanha(smA), smA);
                ypB[p] = fmaf(t2[p], tanha(spB), spB);
                ymB[p] = fmaf(t2[p], tanha(smB), smB);
            }
        }

        // ---- Layer 3: 3 -> 1 (1/2 folded) + tanh-form sigmoid difference ----
        {
            const float s3[3] = {w01.w, w02.w, w10.w};
            float fpA = w00.w, fmA = w00.w, fpB = w00.w, fmB = w00.w;
#pragma unroll
            for (int j = 0; j < 3; j++) {
                fpA = fmaf(ypA[j], s3[j], fpA);
                fmA = fmaf(ymA[j], s3[j], fmA);
                fpB = fmaf(ypB[j], s3[j], fpB);
                fmB = fmaf(ymB[j], s3[j], fmB);
            }
            out[i] = 0.5f * (tanha(fpA) - tanha(fmA));
            if (ok2) out[i2] = 0.5f * (tanha(fpB) - tanha(fmB));
        }
    }
}

extern "C" void kernel_launch(void* const* d_in, const int* in_sizes, int n_in,
                              void* d_out, int out_size)
{
    const float* x  = (const float*)d_in[0];
    const float* a0 = (const float*)d_in[1];
    const float* a1 = (const float*)d_in[2];
    const float* a2 = (const float*)d_in[3];
    const float* b0 = (const float*)d_in[4];
    const float* b1 = (const float*)d_in[5];
    const float* b2 = (const float*)d_in[6];
    const float* b3 = (const float*)d_in[7];
    const float* H0 = (const float*)d_in[8];
    const float* H1 = (const float*)d_in[9];
    const float* H2 = (const float*)d_in[10];
    const float* H3 = (const float*)d_in[11];
    float* out = (float*)d_out;
    int n = in_sizes[0];   // 65536 * 192

    de_kernel<<<NBLK, NTHR>>>(x, a0, a1, a2, b0, b1, b2, b3,
                              H0, H1, H2, H3, out, n);
}

// round 6
// speedup vs baseline: 2.2221x; 2.2221x over previous
#include <cuda_runtime.h>
#include <cuda_bf16.h>

// DensityEstimator: per-channel 1->3->3->3->1 MLP, p = cdf(x+.5) - cdf(x-.5)
// R6: register weights (R2 design) + 2 elems/thread (4 independent tanh
// chains, R4's +32% per-warp throughput) + 64-reg cap so 4 blocks/SM stay
// resident. bm0 eliminated via tm = tp - sh0[j] (exact), 40 weight regs.
// Grid 591: divisible by 3 -> 591*256 % 192 == 0 (channel fixed per thread),
// ~3.99 blocks/SM -> single wave at full reg-limited residency.

#define NCH  192
#define NBLK 591
#define NTHR 256

__device__ __forceinline__ float tanha(float x) {
    float r; asm("tanh.approx.f32 %0, %1;" : "=f"(r) : "f"(x)); return r;
}
__device__ __forceinline__ float softplus_acc(float h) {
    return (h > 15.0f) ? h : log1pf(expf(h));
}

struct W {
    float sh0[3], sh1[9], sh2[9], sh3[3];
    float ta0[3], ta1[3], ta2[3];
    float bp0[3], bb1[3], bb2[3], bb3;
};

// One element, both cdf branches. tm = tp - sh0[j] replaces the bm0 weights.
__device__ __forceinline__ float de_one(float xv, const W& w) {
    float yp[3], ym[3];
#pragma unroll
    for (int j = 0; j < 3; j++) {
        float tp = fmaf(xv, w.sh0[j], w.bp0[j]);   // at x + 0.5
        float tm = tp - w.sh0[j];                  // at x - 0.5 (exact)
        yp[j] = fmaf(w.ta0[j], tanha(tp), tp);
        ym[j] = fmaf(w.ta0[j], tanha(tm), tm);
    }
    float zp[3], zm[3];
#pragma unroll
    for (int p = 0; p < 3; p++) {
        float sp = w.bb1[p], sm = w.bb1[p];
#pragma unroll
        for (int j = 0; j < 3; j++) {
            sp = fmaf(yp[j], w.sh1[j*3 + p], sp);
            sm = fmaf(ym[j], w.sh1[j*3 + p], sm);
        }
        zp[p] = fmaf(w.ta1[p], tanha(sp), sp);
        zm[p] = fmaf(w.ta1[p], tanha(sm), sm);
    }
#pragma unroll
    for (int p = 0; p < 3; p++) {
        float sp = w.bb2[p], sm = w.bb2[p];
#pragma unroll
        for (int j = 0; j < 3; j++) {
            sp = fmaf(zp[j], w.sh2[j*3 + p], sp);
            sm = fmaf(zm[j], w.sh2[j*3 + p], sm);
        }
        yp[p] = fmaf(w.ta2[p], tanha(sp), sp);
        ym[p] = fmaf(w.ta2[p], tanha(sm), sm);
    }
    float fp = w.bb3, fm = w.bb3;
#pragma unroll
    for (int j = 0; j < 3; j++) {
        fp = fmaf(yp[j], w.sh3[j], fp);
        fm = fmaf(ym[j], w.sh3[j], fm);
    }
    return 0.5f * (tanha(fp) - tanha(fm));
}

__global__ void __launch_bounds__(NTHR, 4) de_kernel(
    const float* __restrict__ x,
    const float* __restrict__ a0, const float* __restrict__ a1, const float* __restrict__ a2,
    const float* __restrict__ b0, const float* __restrict__ b1, const float* __restrict__ b2,
    const float* __restrict__ b3,
    const float* __restrict__ H0, const float* __restrict__ H1, const float* __restrict__ H2,
    const float* __restrict__ H3,
    float* __restrict__ out, int n)
{
    const int T  = gridDim.x * blockDim.x;          // 151296, multiple of 192
    const int i0 = blockIdx.x * blockDim.x + threadIdx.x;
    const int c  = i0 % NCH;                        // fixed channel (T % 192 == 0)

    // One-time per-thread weight transform into registers (40 floats).
    W w;
#pragma unroll
    for (int j = 0; j < 3; j++) {
        w.sh0[j] = softplus_acc(__ldg(&H0[c*3 + j]));          // H0: (C,1,3)
        w.sh3[j] = 0.5f * softplus_acc(__ldg(&H3[c*3 + j]));   // H3: (C,3,1), 1/2 folded
        w.ta0[j] = tanhf(__ldg(&a0[c*3 + j]));
        w.ta1[j] = tanhf(__ldg(&a1[c*3 + j]));
        w.ta2[j] = tanhf(__ldg(&a2[c*3 + j]));
        w.bp0[j] = fmaf(0.5f, w.sh0[j], __ldg(&b0[c*3 + j]));  // x+0.5 folded
        w.bb1[j] = __ldg(&b1[c*3 + j]);
        w.bb2[j] = __ldg(&b2[c*3 + j]);
    }
#pragma unroll
    for (int j = 0; j < 9; j++) {
        w.sh1[j] = softplus_acc(__ldg(&H1[c*9 + j]));          // H1: (C,3,3) [i*3+p]
        w.sh2[j] = softplus_acc(__ldg(&H2[c*9 + j]));
    }
    w.bb3 = 0.5f * __ldg(&b3[c]);                              // 1/2 folded

    // Two elements per iteration; i and i+T share the channel.
    for (int i = i0; i < n; i += 2 * T) {
        const int  i2  = i + T;
        const bool ok2 = i2 < n;
        float xa = x[i];
        float xb = x[ok2 ? i2 : i];
        float ra = de_one(xa, w);
        float rb = de_one(xb, w);
        out[i] = ra;
        if (ok2) out[i2] = rb;
    }
}

extern "C" void kernel_launch(void* const* d_in, const int* in_sizes, int n_in,
                              void* d_out, int out_size)
{
    const float* x  = (const float*)d_in[0];
    const float* a0 = (const float*)d_in[1];
    const float* a1 = (const float*)d_in[2];
    const float* a2 = (const float*)d_in[3];
    const float* b0 = (const float*)d_in[4];
    const float* b1 = (const float*)d_in[5];
    const float* b2 = (const float*)d_in[6];
    const float* b3 = (const float*)d_in[7];
    const float* H0 = (const float*)d_in[8];
    const float* H1 = (const float*)d_in[9];
    const float* H2 = (const float*)d_in[10];
    const float* H3 = (const float*)d_in[11];
    float* out = (float*)d_out;
    int n = in_sizes[0];   // 65536 * 192

    de_kernel<<<NBLK, NTHR>>>(x, a0, a1, a2, b0, b1, b2, b3,
                              H0, H1, H2, H3, out, n);
}